// round 6
// baseline (speedup 1.0000x reference)
#include <cuda_runtime.h>
#include <cstdint>

#define BATCH 8
#define SEQ 2048
#define DIM 1024
#define M_TOTAL (BATCH * SEQ)

// GEMM tiling
#define BM 128
#define BN 256
#define BK 32
#define KTILES (DIM / BK)        // 32
#define LDT 36                   // padded smem row (floats); frag LDS conflict-free
#define STAGEF ((BM + BN) * LDT) // floats per stage
#define NSTAGES 4
#define SMEM_BYTES (NSTAGES * STAGEF * 4)   // 221184

// scan chunking
#define CHUNKS 16
#define CLEN (SEQ / CHUNKS)      // 128

// -------------------- scratch (static device globals, no alloc) ------------
__device__ float g_u[(size_t)M_TOTAL * DIM];   // u, then h in place
__device__ float g_carry[BATCH * CHUNKS * DIM];

// -------------------- helpers ----------------------------------------------
__device__ __forceinline__ uint32_t smem_u32(const void* p) {
    uint32_t a;
    asm("{ .reg .u64 t; cvta.to.shared.u64 t, %1; cvt.u32.u64 %0, t; }" : "=r"(a) : "l"(p));
    return a;
}
__device__ __forceinline__ uint32_t rtf32_u(float x) {
    uint32_t r;
    asm("cvt.rna.tf32.f32 %0, %1;" : "=r"(r) : "f"(x));
    return r;
}
#define CP_ASYNC16(dst, src) \
    asm volatile("cp.async.cg.shared.global [%0], [%1], 16;" :: "r"(dst), "l"(src))

__device__ __forceinline__ void mma_tf32(float* d, const uint32_t* a, const uint32_t* b) {
    asm volatile(
        "mma.sync.aligned.m16n8k8.row.col.f32.tf32.tf32.f32 "
        "{%0,%1,%2,%3}, {%4,%5,%6,%7}, {%8,%9}, {%0,%1,%2,%3};"
        : "+f"(d[0]), "+f"(d[1]), "+f"(d[2]), "+f"(d[3])
        : "r"(a[0]), "r"(a[1]), "r"(a[2]), "r"(a[3]), "r"(b[0]), "r"(b[1]));
}

// -------------------- tf32 mma.sync GEMM -----------------------------------
// C[m,n] = sum_k A[m,k]*B[n,k] (+bias[n]). A: MxK row-major, B: NxK row-major.
// Warp tile 64x64; operands tf32-rounded in-register (cvt.rna).
__global__ void __launch_bounds__(256, 1)
gemm_tf32mma(const float* __restrict__ A, const float* __restrict__ Bm,
             const float* __restrict__ bias, float* __restrict__ C,
             int add_bias)
{
    extern __shared__ float sm[];
    const int tid = threadIdx.x;
    const int wid = tid >> 5, lid = tid & 31;
    const int g = lid >> 2, tg = lid & 3;       // mma quad coords
    const int warp_m = wid >> 2;                // 0..1 (64 rows)
    const int warp_n = wid & 3;                 // 0..3 (64 cols)
    const int bm = blockIdx.y * BM, bn = blockIdx.x * BN;

    const uint32_t sbase = smem_u32(sm);

    float acc[4][8][4];
#pragma unroll
    for (int mi = 0; mi < 4; mi++)
#pragma unroll
        for (int ni = 0; ni < 8; ni++)
#pragma unroll
            for (int q = 0; q < 4; q++) acc[mi][ni][q] = 0.0f;

    // ---- stage loader: A 128x32 (4 iters), B 256x32 (8 iters) ----
    auto load_stage = [&](int buf, int kt) {
        const uint32_t sa = sbase + (uint32_t)(buf * STAGEF) * 4u;
        const uint32_t sb2 = sa + (uint32_t)(BM * LDT) * 4u;
        const float* Ag = A + (size_t)bm * DIM + kt * BK;
        const float* Bg = Bm + (size_t)bn * DIM + kt * BK;
#pragma unroll
        for (int it = 0; it < 4; it++) {
            int idx = tid + it * 256;
            int r = idx >> 3, c = idx & 7;
            CP_ASYNC16(sa + (uint32_t)(r * LDT + c * 4) * 4u, Ag + (size_t)r * DIM + c * 4);
        }
#pragma unroll
        for (int it = 0; it < 8; it++) {
            int idx = tid + it * 256;
            int r = idx >> 3, c = idx & 7;
            CP_ASYNC16(sb2 + (uint32_t)(r * LDT + c * 4) * 4u, Bg + (size_t)r * DIM + c * 4);
        }
        asm volatile("cp.async.commit_group;" ::: "memory");
    };

    load_stage(0, 0);
    load_stage(1, 1);

    for (int j = 0; j < KTILES; j++) {
        if (j >= KTILES - 2) asm volatile("cp.async.wait_group 0;" ::: "memory");
        else                 asm volatile("cp.async.wait_group 1;" ::: "memory");
        __syncthreads();

        if (j + 2 < KTILES) load_stage((j + 2) & (NSTAGES - 1), j + 2);

        const float* As = sm + (j & (NSTAGES - 1)) * STAGEF;
        const float* Bs = As + BM * LDT;

#pragma unroll
        for (int ks = 0; ks < 4; ks++) {
            const int k0 = ks * 8;
            uint32_t a[4][4], b[8][2];
#pragma unroll
            for (int mi = 0; mi < 4; mi++) {
                const int r = warp_m * 64 + mi * 16 + g;
                a[mi][0] = rtf32_u(As[r * LDT + k0 + tg]);
                a[mi][1] = rtf32_u(As[(r + 8) * LDT + k0 + tg]);
                a[mi][2] = rtf32_u(As[r * LDT + k0 + tg + 4]);
                a[mi][3] = rtf32_u(As[(r + 8) * LDT + k0 + tg + 4]);
            }
#pragma unroll
            for (int ni = 0; ni < 8; ni++) {
                const int n = warp_n * 64 + ni * 8 + g;
                b[ni][0] = rtf32_u(Bs[n * LDT + k0 + tg]);
                b[ni][1] = rtf32_u(Bs[n * LDT + k0 + tg + 4]);
            }
#pragma unroll
            for (int mi = 0; mi < 4; mi++)
#pragma unroll
                for (int ni = 0; ni < 8; ni++)
                    mma_tf32(acc[mi][ni], a[mi], b[ni]);
        }
        // no trailing __syncthreads: 4-stage ring, write target at iter j+1
        // was last read at iter j-1; two intervening top-syncs order it.
    }

    // ---- epilogue ----
#pragma unroll
    for (int mi = 0; mi < 4; mi++) {
        const int r0 = bm + warp_m * 64 + mi * 16 + g;
#pragma unroll
        for (int ni = 0; ni < 8; ni++) {
            const int cc = bn + warp_n * 64 + ni * 8 + 2 * tg;
            float2 v0 = make_float2(acc[mi][ni][0], acc[mi][ni][1]);
            float2 v1 = make_float2(acc[mi][ni][2], acc[mi][ni][3]);
            if (add_bias) {
                const float b0 = bias[cc], b1 = bias[cc + 1];
                v0.x += b0; v0.y += b1;
                v1.x += b0; v1.y += b1;
            }
            *reinterpret_cast<float2*>(&C[(size_t)r0 * DIM + cc]) = v0;
            *reinterpret_cast<float2*>(&C[(size_t)(r0 + 8) * DIM + cc]) = v1;
        }
    }
}

// -------------------- chunked diagonal scan (in place on g_u) --------------
__global__ void __launch_bounds__(256)
scan_carry(const float* __restrict__ Avec)
{
    const int idx = blockIdx.x * blockDim.x + threadIdx.x;  // 131072
    const int n = idx & (DIM - 1);
    const int ch = (idx >> 10) & (CHUNKS - 1);
    const int b = idx >> 14;
    const float a = Avec[n];
    const float* u = g_u + ((size_t)b * SEQ + (size_t)ch * CLEN) * DIM + n;
    float h = 0.0f;
#pragma unroll 8
    for (int t = 0; t < CLEN; t++) h = fmaf(a, h, u[(size_t)t * DIM]);
    g_carry[idx] = h;
}

// prefix computed inline from carries (<=15 L2-resident reads), then replay
__global__ void __launch_bounds__(256)
scan_apply(const float* __restrict__ Avec)
{
    const int idx = blockIdx.x * blockDim.x + threadIdx.x;  // 131072
    const int n = idx & (DIM - 1);
    const int ch = (idx >> 10) & (CHUNKS - 1);
    const int b = idx >> 14;
    const float a = Avec[n];

    float aL = a;
#pragma unroll
    for (int s = 0; s < 7; s++) aL *= aL;   // a^128

    float h = 0.0f;  // prefix entering this chunk
    for (int i = 0; i < ch; i++)
        h = fmaf(aL, h, g_carry[(b * CHUNKS + i) * DIM + n]);

    float* u = g_u + ((size_t)b * SEQ + (size_t)ch * CLEN) * DIM + n;
#pragma unroll 8
    for (int t = 0; t < CLEN; t++) {
        h = fmaf(a, h, u[(size_t)t * DIM]);
        u[(size_t)t * DIM] = h;
    }
}

// -------------------- launch -----------------------------------------------
extern "C" void kernel_launch(void* const* d_in, const int* in_sizes, int n_in,
                              void* d_out, int out_size)
{
    const float* x    = (const float*)d_in[0];
    const float* Avec = (const float*)d_in[1];
    const float* Bmat = (const float*)d_in[2];
    const float* Wmat = (const float*)d_in[3];
    const float* bias = (const float*)d_in[4];
    float* out = (float*)d_out;

    float* u = nullptr;
    cudaGetSymbolAddress((void**)&u, g_u);

    cudaFuncSetAttribute(gemm_tf32mma, cudaFuncAttributeMaxDynamicSharedMemorySize, SMEM_BYTES);

    dim3 grid(DIM / BN, M_TOTAL / BM);  // (4, 128)

    // u = x @ B^T
    gemm_tf32mma<<<grid, 256, SMEM_BYTES>>>(x, Bmat, nullptr, u, 0);

    // h_t = a h_{t-1} + u_t, chunked, in place
    scan_carry<<<(BATCH * CHUNKS * DIM) / 256, 256>>>(Avec);
    scan_apply<<<(BATCH * CHUNKS * DIM) / 256, 256>>>(Avec);

    // y = h @ W^T + b
    gemm_tf32mma<<<grid, 256, SMEM_BYTES>>>(u, Wmat, bias, out, 1);
}

// round 7
// speedup vs baseline: 1.1450x; 1.1450x over previous
#include <cuda_runtime.h>
#include <cstdint>

#define BATCH 8
#define SEQ 2048
#define DIM 1024
#define M_TOTAL (BATCH * SEQ)

// GEMM tiling (R4 shape: occ 2, 16 warps/SM)
#define BM 128
#define BN 128
#define BK 32
#define KTILES (DIM / BK)        // 32
#define LDT 36                   // padded smem row (floats); frag LDS conflict-free
#define STAGEF ((BM + BN) * LDT) // floats per stage
#define NSTAGES 3
#define SMEM_BYTES (NSTAGES * STAGEF * 4)   // 110592

// scan chunking
#define CHUNKS 16
#define CLEN (SEQ / CHUNKS)      // 128

// -------------------- scratch (static device globals, no alloc) ------------
__device__ float g_u[(size_t)M_TOTAL * DIM];   // u, then h (tf32-rounded) in place
__device__ float g_x[(size_t)M_TOTAL * DIM];   // tf32-rounded x
__device__ float g_Br[DIM * DIM];              // tf32-rounded B
__device__ float g_Wr[DIM * DIM];              // tf32-rounded W
__device__ float g_carry[BATCH * CHUNKS * DIM];

// -------------------- helpers ----------------------------------------------
__device__ __forceinline__ uint32_t smem_u32(const void* p) {
    uint32_t a;
    asm("{ .reg .u64 t; cvta.to.shared.u64 t, %1; cvt.u32.u64 %0, t; }" : "=r"(a) : "l"(p));
    return a;
}
__device__ __forceinline__ float rtf32(float x) {
    uint32_t r;
    asm("cvt.rna.tf32.f32 %0, %1;" : "=r"(r) : "f"(x));
    return __uint_as_float(r);
}
#define CP_ASYNC16(dst, src) \
    asm volatile("cp.async.cg.shared.global [%0], [%1], 16;" :: "r"(dst), "l"(src))

__device__ __forceinline__ void mma_tf32(float* d, const uint32_t* a, const uint32_t* b) {
    asm volatile(
        "mma.sync.aligned.m16n8k8.row.col.f32.tf32.tf32.f32 "
        "{%0,%1,%2,%3}, {%4,%5,%6,%7}, {%8,%9}, {%0,%1,%2,%3};"
        : "+f"(d[0]), "+f"(d[1]), "+f"(d[2]), "+f"(d[3])
        : "r"(a[0]), "r"(a[1]), "r"(a[2]), "r"(a[3]), "r"(b[0]), "r"(b[1]));
}

// -------------------- tf32 mma.sync GEMM (inputs pre-rounded) ---------------
// C[m,n] = sum_k A[m,k]*B[n,k] (+bias[n]). A: MxK row-major, B: NxK row-major.
__global__ void __launch_bounds__(256, 2)
gemm_tf32mma(const float* __restrict__ A, const float* __restrict__ Bm,
             const float* __restrict__ bias, float* __restrict__ C,
             int add_bias)
{
    extern __shared__ float sm[];
    const int tid = threadIdx.x;
    const int wid = tid >> 5, lid = tid & 31;
    const int g = lid >> 2, tg = lid & 3;       // mma quad coords
    const int warp_m = wid >> 2;                // 0..1 (64 rows)
    const int warp_n = wid & 3;                 // 0..3 (32 cols)
    const int bm = blockIdx.y * BM, bn = blockIdx.x * BN;

    const uint32_t sbase = smem_u32(sm);
    const uint32_t* smu = reinterpret_cast<const uint32_t*>(sm);

    float acc[4][4][4];
#pragma unroll
    for (int mi = 0; mi < 4; mi++)
#pragma unroll
        for (int ni = 0; ni < 4; ni++)
#pragma unroll
            for (int q = 0; q < 4; q++) acc[mi][ni][q] = 0.0f;

    auto load_stage = [&](int buf, int kt) {
        const uint32_t sa = sbase + (uint32_t)(buf * STAGEF) * 4u;
        const uint32_t sb2 = sa + (uint32_t)(BM * LDT) * 4u;
        const float* Ag = A + (size_t)bm * DIM + kt * BK;
        const float* Bg = Bm + (size_t)bn * DIM + kt * BK;
#pragma unroll
        for (int it = 0; it < 4; it++) {        // A: 128 rows x 8 chunks of 16B
            int idx = tid + it * 256;
            int r = idx >> 3, c = idx & 7;
            CP_ASYNC16(sa + (uint32_t)(r * LDT + c * 4) * 4u, Ag + (size_t)r * DIM + c * 4);
        }
#pragma unroll
        for (int it = 0; it < 4; it++) {        // B: 128 rows x 8 chunks
            int idx = tid + it * 256;
            int r = idx >> 3, c = idx & 7;
            CP_ASYNC16(sb2 + (uint32_t)(r * LDT + c * 4) * 4u, Bg + (size_t)r * DIM + c * 4);
        }
        asm volatile("cp.async.commit_group;" ::: "memory");
    };

    load_stage(0, 0);
    load_stage(1, 1);

    for (int j = 0; j < KTILES; j++) {
        if (j == KTILES - 1) asm volatile("cp.async.wait_group 0;" ::: "memory");
        else                 asm volatile("cp.async.wait_group 1;" ::: "memory");
        __syncthreads();

        if (j + 2 < KTILES) load_stage((j + 2) % NSTAGES, j + 2);

        const uint32_t* As = smu + (j % NSTAGES) * STAGEF;
        const uint32_t* Bs = As + BM * LDT;

#pragma unroll
        for (int ks = 0; ks < 4; ks++) {
            const int k0 = ks * 8;
            uint32_t a[4][4], b[4][2];
#pragma unroll
            for (int mi = 0; mi < 4; mi++) {
                const int r = warp_m * 64 + mi * 16 + g;
                a[mi][0] = As[r * LDT + k0 + tg];
                a[mi][1] = As[(r + 8) * LDT + k0 + tg];
                a[mi][2] = As[r * LDT + k0 + tg + 4];
                a[mi][3] = As[(r + 8) * LDT + k0 + tg + 4];
            }
#pragma unroll
            for (int ni = 0; ni < 4; ni++) {
                const int n = warp_n * 32 + ni * 8 + g;
                b[ni][0] = Bs[n * LDT + k0 + tg];
                b[ni][1] = Bs[n * LDT + k0 + tg + 4];
            }
#pragma unroll
            for (int mi = 0; mi < 4; mi++)
#pragma unroll
                for (int ni = 0; ni < 4; ni++)
                    mma_tf32(acc[mi][ni], a[mi], b[ni]);
        }
        // no trailing sync: the buffer cp.async writes at iter j+1 was last
        // read in compute of iter j-1; the full barrier at top of iter j+1
        // orders those reads (consumed into registers) before the writes.
    }

    // ---- epilogue ----
#pragma unroll
    for (int mi = 0; mi < 4; mi++) {
        const int r0 = bm + warp_m * 64 + mi * 16 + g;
#pragma unroll
        for (int ni = 0; ni < 4; ni++) {
            const int cc = bn + warp_n * 32 + ni * 8 + 2 * tg;
            float2 v0 = make_float2(acc[mi][ni][0], acc[mi][ni][1]);
            float2 v1 = make_float2(acc[mi][ni][2], acc[mi][ni][3]);
            if (add_bias) {
                const float b0 = bias[cc], b1 = bias[cc + 1];
                v0.x += b0; v0.y += b1;
                v1.x += b0; v1.y += b1;
            }
            *reinterpret_cast<float2*>(&C[(size_t)r0 * DIM + cc]) = v0;
            *reinterpret_cast<float2*>(&C[(size_t)(r0 + 8) * DIM + cc]) = v1;
        }
    }
}

// -------------------- tf32 rounding prepass --------------------------------
__global__ void __launch_bounds__(256)
round_tf32_kernel(const float4* __restrict__ in, float4* __restrict__ out, int n4)
{
    int i = blockIdx.x * blockDim.x + threadIdx.x;
    if (i < n4) {
        float4 v = in[i];
        v.x = rtf32(v.x); v.y = rtf32(v.y); v.z = rtf32(v.z); v.w = rtf32(v.w);
        out[i] = v;
    }
}

// -------------------- chunked diagonal scan (in place on g_u) --------------
__global__ void __launch_bounds__(256)
scan_carry(const float* __restrict__ Avec)
{
    const int idx = blockIdx.x * blockDim.x + threadIdx.x;  // 131072
    const int n = idx & (DIM - 1);
    const int ch = (idx >> 10) & (CHUNKS - 1);
    const int b = idx >> 14;
    const float a = Avec[n];
    const float* u = g_u + ((size_t)b * SEQ + (size_t)ch * CLEN) * DIM + n;
    float h = 0.0f;
#pragma unroll 8
    for (int t = 0; t < CLEN; t++) h = fmaf(a, h, u[(size_t)t * DIM]);
    g_carry[idx] = h;
}

// prefix from carries (<=15 L2-resident reads), replay, store tf32-rounded h
__global__ void __launch_bounds__(256)
scan_apply(const float* __restrict__ Avec)
{
    const int idx = blockIdx.x * blockDim.x + threadIdx.x;  // 131072
    const int n = idx & (DIM - 1);
    const int ch = (idx >> 10) & (CHUNKS - 1);
    const int b = idx >> 14;
    const float a = Avec[n];

    float aL = a;
#pragma unroll
    for (int s = 0; s < 7; s++) aL *= aL;   // a^128

    float h = 0.0f;  // prefix entering this chunk
    for (int i = 0; i < ch; i++)
        h = fmaf(aL, h, g_carry[(b * CHUNKS + i) * DIM + n]);

    float* u = g_u + ((size_t)b * SEQ + (size_t)ch * CLEN) * DIM + n;
#pragma unroll 8
    for (int t = 0; t < CLEN; t++) {
        h = fmaf(a, h, u[(size_t)t * DIM]);
        u[(size_t)t * DIM] = rtf32(h);
    }
}

// -------------------- launch -----------------------------------------------
extern "C" void kernel_launch(void* const* d_in, const int* in_sizes, int n_in,
                              void* d_out, int out_size)
{
    const float* x    = (const float*)d_in[0];
    const float* Avec = (const float*)d_in[1];
    const float* Bmat = (const float*)d_in[2];
    const float* Wmat = (const float*)d_in[3];
    const float* bias = (const float*)d_in[4];
    float* out = (float*)d_out;

    float *u, *xr, *Br, *Wr;
    cudaGetSymbolAddress((void**)&u, g_u);
    cudaGetSymbolAddress((void**)&xr, g_x);
    cudaGetSymbolAddress((void**)&Br, g_Br);
    cudaGetSymbolAddress((void**)&Wr, g_Wr);

    cudaFuncSetAttribute(gemm_tf32mma, cudaFuncAttributeMaxDynamicSharedMemorySize, SMEM_BYTES);

    // pre-round inputs to tf32 (rna): removes all cvt from GEMM hot loops
    const int nx4 = M_TOTAL * DIM / 4;
    const int nw4 = DIM * DIM / 4;
    round_tf32_kernel<<<(nx4 + 255) / 256, 256>>>((const float4*)x, (float4*)xr, nx4);
    round_tf32_kernel<<<(nw4 + 255) / 256, 256>>>((const float4*)Bmat, (float4*)Br, nw4);
    round_tf32_kernel<<<(nw4 + 255) / 256, 256>>>((const float4*)Wmat, (float4*)Wr, nw4);

    dim3 grid(DIM / BN, M_TOTAL / BM);  // (8, 128)

    // u = x_r @ B_r^T
    gemm_tf32mma<<<grid, 256, SMEM_BYTES>>>(xr, Br, nullptr, u, 0);

    // h_t = a h_{t-1} + u_t, chunked, in place; h stored tf32-rounded
    scan_carry<<<(BATCH * CHUNKS * DIM) / 256, 256>>>(Avec);
    scan_apply<<<(BATCH * CHUNKS * DIM) / 256, 256>>>(Avec);

    // y = h_r @ W_r^T + b
    gemm_tf32mma<<<grid, 256, SMEM_BYTES>>>(u, Wr, bias, out, 1);
}

// round 9
// speedup vs baseline: 1.2233x; 1.0684x over previous
#include <cuda_runtime.h>
#include <cstdint>

#define BATCH 8
#define SEQ 2048
#define DIM 1024
#define M_TOTAL (BATCH * SEQ)

// GEMM tiling (occ 2, 16 warps/SM)
#define BM 128
#define BN 128
#define BK 32
#define KTILES (DIM / BK)        // 32
#define LDT 36                   // padded smem row (floats); LDSM phases conflict-free
#define STAGEF ((BM + BN) * LDT) // floats per stage
#define NSTAGES 3
#define SMEM_BYTES (NSTAGES * STAGEF * 4)   // 110592

// scan chunking
#define CHUNKS 16
#define CLEN (SEQ / CHUNKS)      // 128

// -------------------- scratch (static device globals, no alloc) ------------
__device__ float g_u[(size_t)M_TOTAL * DIM];   // u, then h (tf32-rounded) in place
__device__ float g_x[(size_t)M_TOTAL * DIM];   // tf32-rounded x
__device__ float g_Br[DIM * DIM];              // tf32-rounded B
__device__ float g_Wr[DIM * DIM];              // tf32-rounded W
__device__ float g_carry[BATCH * CHUNKS * DIM];

// -------------------- helpers ----------------------------------------------
__device__ __forceinline__ uint32_t smem_u32(const void* p) {
    uint32_t a;
    asm("{ .reg .u64 t; cvta.to.shared.u64 t, %1; cvt.u32.u64 %0, t; }" : "=r"(a) : "l"(p));
    return a;
}
__device__ __forceinline__ float rtf32(float x) {
    uint32_t r;
    asm("cvt.rna.tf32.f32 %0, %1;" : "=r"(r) : "f"(x));
    return __uint_as_float(r);
}
#define CP_ASYNC16(dst, src) \
    asm volatile("cp.async.cg.shared.global [%0], [%1], 16;" :: "r"(dst), "l"(src))

__device__ __forceinline__ void ldsm4(uint32_t& r0, uint32_t& r1, uint32_t& r2,
                                      uint32_t& r3, uint32_t addr) {
    asm volatile("ldmatrix.sync.aligned.m8n8.x4.shared.b16 {%0,%1,%2,%3}, [%4];"
                 : "=r"(r0), "=r"(r1), "=r"(r2), "=r"(r3) : "r"(addr));
}

__device__ __forceinline__ void mma_tf32(float* d, const uint32_t* a, const uint32_t* b) {
    asm volatile(
        "mma.sync.aligned.m16n8k8.row.col.f32.tf32.tf32.f32 "
        "{%0,%1,%2,%3}, {%4,%5,%6,%7}, {%8,%9}, {%0,%1,%2,%3};"
        : "+f"(d[0]), "+f"(d[1]), "+f"(d[2]), "+f"(d[3])
        : "r"(a[0]), "r"(a[1]), "r"(a[2]), "r"(a[3]), "r"(b[0]), "r"(b[1]));
}

// -------------------- tf32 mma.sync GEMM (inputs pre-rounded) ---------------
// C[m,n] = sum_k A[m,k]*B[n,k] (+bias[n]). A: MxK row-major, B: NxK row-major.
// Fragments loaded via ldmatrix.x4 (1 LDSM feeds 4-8 MMAs).
__global__ void __launch_bounds__(256, 2)
gemm_tf32mma(const float* __restrict__ A, const float* __restrict__ Bm,
             const float* __restrict__ bias, float* __restrict__ C,
             int add_bias)
{
    extern __shared__ float sm[];
    const int tid = threadIdx.x;
    const int wid = tid >> 5, lid = tid & 31;
    const int g = lid >> 2, tg = lid & 3;       // mma quad coords
    const int warp_m = wid >> 2;                // 0..1 (64 rows)
    const int warp_n = wid & 3;                 // 0..3 (32 cols)
    const int bm = blockIdx.y * BM, bn = blockIdx.x * BN;

    const uint32_t sbase = smem_u32(sm);

    // ldmatrix per-lane source rows/cols
    // A x4 tiles: (r0,k0),(r0+8,k0),(r0,k0+4),(r0+8,k0+4)
    const int laneRowA = lid & 15;               // rows r0..r0+15
    const int laneColA = (lid >> 4) << 2;        // k0 or k0+4
    // B x4 tiles: (n0,k0),(n0,k0+4),(n0+8,k0),(n0+8,k0+4)
    const int laneRowB = (lid & 7) + ((lid >> 4) << 3);
    const int laneColB = ((lid >> 3) & 1) << 2;

    const uint32_t aoff = (uint32_t)((warp_m * 64 + laneRowA) * LDT + laneColA) * 4u;
    const uint32_t boff = (uint32_t)((BM + warp_n * 32 + laneRowB) * LDT + laneColB) * 4u;

    float acc[4][4][4];
#pragma unroll
    for (int mi = 0; mi < 4; mi++)
#pragma unroll
        for (int ni = 0; ni < 4; ni++)
#pragma unroll
            for (int q = 0; q < 4; q++) acc[mi][ni][q] = 0.0f;

    auto load_stage = [&](int buf, int kt) {
        const uint32_t sa = sbase + (uint32_t)(buf * STAGEF) * 4u;
        const uint32_t sb2 = sa + (uint32_t)(BM * LDT) * 4u;
        const float* Ag = A + (size_t)bm * DIM + kt * BK;
        const float* Bg = Bm + (size_t)bn * DIM + kt * BK;
#pragma unroll
        for (int it = 0; it < 4; it++) {        // A: 128 rows x 8 chunks of 16B
            int idx = tid + it * 256;
            int r = idx >> 3, c = idx & 7;
            CP_ASYNC16(sa + (uint32_t)(r * LDT + c * 4) * 4u, Ag + (size_t)r * DIM + c * 4);
        }
#pragma unroll
        for (int it = 0; it < 4; it++) {        // B: 128 rows x 8 chunks
            int idx = tid + it * 256;
            int r = idx >> 3, c = idx & 7;
            CP_ASYNC16(sb2 + (uint32_t)(r * LDT + c * 4) * 4u, Bg + (size_t)r * DIM + c * 4);
        }
        asm volatile("cp.async.commit_group;" ::: "memory");
    };

    load_stage(0, 0);
    load_stage(1, 1);

    for (int j = 0; j < KTILES; j++) {
        if (j == KTILES - 1) asm volatile("cp.async.wait_group 0;" ::: "memory");
        else                 asm volatile("cp.async.wait_group 1;" ::: "memory");
        __syncthreads();

        if (j + 2 < KTILES) load_stage((j + 2) % NSTAGES, j + 2);

        const uint32_t stg = sbase + (uint32_t)((j % NSTAGES) * STAGEF) * 4u;
        const uint32_t sa = stg + aoff;
        const uint32_t sb2 = stg + boff;

#pragma unroll
        for (int ks = 0; ks < 4; ks++) {
            const uint32_t kb = (uint32_t)(ks * 8) * 4u;   // k0 in bytes
            uint32_t a[4][4], b[4][2];
#pragma unroll
            for (int mi = 0; mi < 4; mi++)
                ldsm4(a[mi][0], a[mi][1], a[mi][2], a[mi][3],
                      sa + kb + (uint32_t)(mi * 16 * LDT) * 4u);
            ldsm4(b[0][0], b[0][1], b[1][0], b[1][1], sb2 + kb);
            ldsm4(b[2][0], b[2][1], b[3][0], b[3][1],
                  sb2 + kb + (uint32_t)(16 * LDT) * 4u);
#pragma unroll
            for (int mi = 0; mi < 4; mi++)
#pragma unroll
                for (int ni = 0; ni < 4; ni++)
                    mma_tf32(acc[mi][ni], a[mi], b[ni]);
        }
        // no trailing sync: 3-stage ring; the buffer written at iter j+1 was
        // last read at iter j-1, ordered by the barrier at top of iter j+1.
    }

    // ---- epilogue ----
#pragma unroll
    for (int mi = 0; mi < 4; mi++) {
        const int r0 = bm + warp_m * 64 + mi * 16 + g;
#pragma unroll
        for (int ni = 0; ni < 4; ni++) {
            const int cc = bn + warp_n * 32 + ni * 8 + 2 * tg;
            float2 v0 = make_float2(acc[mi][ni][0], acc[mi][ni][1]);
            float2 v1 = make_float2(acc[mi][ni][2], acc[mi][ni][3]);
            if (add_bias) {
                const float b0 = bias[cc], b1 = bias[cc + 1];
                v0.x += b0; v0.y += b1;
                v1.x += b0; v1.y += b1;
            }
            *reinterpret_cast<float2*>(&C[(size_t)r0 * DIM + cc]) = v0;
            *reinterpret_cast<float2*>(&C[(size_t)(r0 + 8) * DIM + cc]) = v1;
        }
    }
}

// -------------------- tf32 rounding prepass --------------------------------
__global__ void __launch_bounds__(256)
round_tf32_kernel(const float4* __restrict__ in, float4* __restrict__ out, int n4)
{
    int i = blockIdx.x * blockDim.x + threadIdx.x;
    if (i < n4) {
        float4 v = in[i];
        v.x = rtf32(v.x); v.y = rtf32(v.y); v.z = rtf32(v.z); v.w = rtf32(v.w);
        out[i] = v;
    }
}

// -------------------- chunked diagonal scan (in place on g_u) --------------
__global__ void __launch_bounds__(256)
scan_carry(const float* __restrict__ Avec)
{
    const int idx = blockIdx.x * blockDim.x + threadIdx.x;  // 131072
    const int n = idx & (DIM - 1);
    const int ch = (idx >> 10) & (CHUNKS - 1);
    const int b = idx >> 14;
    const float a = Avec[n];
    const float* u = g_u + ((size_t)b * SEQ + (size_t)ch * CLEN) * DIM + n;
    float h = 0.0f;
#pragma unroll 8
    for (int t = 0; t < CLEN; t++) h = fmaf(a, h, u[(size_t)t * DIM]);
    g_carry[idx] = h;
}

// prefix from carries (<=15 L2-resident reads), replay, store tf32-rounded h
__global__ void __launch_bounds__(256)
scan_apply(const float* __restrict__ Avec)
{
    const int idx = blockIdx.x * blockDim.x + threadIdx.x;  // 131072
    const int n = idx & (DIM - 1);
    const int ch = (idx >> 10) & (CHUNKS - 1);
    const int b = idx >> 14;
    const float a = Avec[n];

    float aL = a;
#pragma unroll
    for (int s = 0; s < 7; s++) aL *= aL;   // a^128

    float h = 0.0f;  // prefix entering this chunk
    for (int i = 0; i < ch; i++)
        h = fmaf(aL, h, g_carry[(b * CHUNKS + i) * DIM + n]);

    float* u = g_u + ((size_t)b * SEQ + (size_t)ch * CLEN) * DIM + n;
#pragma unroll 8
    for (int t = 0; t < CLEN; t++) {
        h = fmaf(a, h, u[(size_t)t * DIM]);
        u[(size_t)t * DIM] = rtf32(h);
    }
}

// -------------------- launch -----------------------------------------------
extern "C" void kernel_launch(void* const* d_in, const int* in_sizes, int n_in,
                              void* d_out, int out_size)
{
    const float* x    = (const float*)d_in[0];
    const float* Avec = (const float*)d_in[1];
    const float* Bmat = (const float*)d_in[2];
    const float* Wmat = (const float*)d_in[3];
    const float* bias = (const float*)d_in[4];
    float* out = (float*)d_out;

    float *u, *xr, *Br, *Wr;
    cudaGetSymbolAddress((void**)&u, g_u);
    cudaGetSymbolAddress((void**)&xr, g_x);
    cudaGetSymbolAddress((void**)&Br, g_Br);
    cudaGetSymbolAddress((void**)&Wr, g_Wr);

    cudaFuncSetAttribute(gemm_tf32mma, cudaFuncAttributeMaxDynamicSharedMemorySize, SMEM_BYTES);

    // pre-round inputs to tf32 (rna): keeps cvt out of GEMM hot loops
    const int nx4 = M_TOTAL * DIM / 4;
    const int nw4 = DIM * DIM / 4;
    round_tf32_kernel<<<(nx4 + 255) / 256, 256>>>((const float4*)x, (float4*)xr, nx4);
    round_tf32_kernel<<<(nw4 + 255) / 256, 256>>>((const float4*)Bmat, (float4*)Br, nw4);
    round_tf32_kernel<<<(nw4 + 255) / 256, 256>>>((const float4*)Wmat, (float4*)Wr, nw4);

    dim3 grid(DIM / BN, M_TOTAL / BM);  // (8, 128)

    // u = x_r @ B_r^T
    gemm_tf32mma<<<grid, 256, SMEM_BYTES>>>(xr, Br, nullptr, u, 0);

    // h_t = a h_{t-1} + u_t, chunked, in place; h stored tf32-rounded
    scan_carry<<<(BATCH * CHUNKS * DIM) / 256, 256>>>(Avec);
    scan_apply<<<(BATCH * CHUNKS * DIM) / 256, 256>>>(Avec);

    // y = h_r @ W_r^T + b
    gemm_tf32mma<<<grid, 256, SMEM_BYTES>>>(u, Wr, bias, out, 1);
}

// round 10
// speedup vs baseline: 1.2763x; 1.0433x over previous
#include <cuda_runtime.h>
#include <cstdint>

#define BATCH 8
#define SEQ 2048
#define DIM 1024
#define M_TOTAL (BATCH * SEQ)

// GEMM tiling: 512 threads, 4x4 warp grid, 32x32 warp tile, occ 2 (32 warps/SM)
#define BM 128
#define BN 128
#define BK 32
#define KTILES (DIM / BK)        // 32
#define LDT 36                   // padded smem row (floats); LDSM phases conflict-free
#define STAGEF ((BM + BN) * LDT) // floats per stage
#define NSTAGES 3
#define SMEM_BYTES (NSTAGES * STAGEF * 4)   // 110592

// scan chunking
#define CHUNKS 16
#define CLEN (SEQ / CHUNKS)      // 128

// -------------------- scratch (static device globals, no alloc) ------------
__device__ float g_u[(size_t)M_TOTAL * DIM];   // u, then h (tf32-rounded) in place
__device__ float g_x[(size_t)M_TOTAL * DIM];   // tf32-rounded x
__device__ float g_Br[DIM * DIM];              // tf32-rounded B
__device__ float g_Wr[DIM * DIM];              // tf32-rounded W
__device__ float g_carry[BATCH * CHUNKS * DIM];

// -------------------- helpers ----------------------------------------------
__device__ __forceinline__ uint32_t smem_u32(const void* p) {
    uint32_t a;
    asm("{ .reg .u64 t; cvta.to.shared.u64 t, %1; cvt.u32.u64 %0, t; }" : "=r"(a) : "l"(p));
    return a;
}
__device__ __forceinline__ float rtf32(float x) {
    uint32_t r;
    asm("cvt.rna.tf32.f32 %0, %1;" : "=r"(r) : "f"(x));
    return __uint_as_float(r);
}
#define CP_ASYNC16(dst, src) \
    asm volatile("cp.async.cg.shared.global [%0], [%1], 16;" :: "r"(dst), "l"(src))

__device__ __forceinline__ void ldsm4(uint32_t& r0, uint32_t& r1, uint32_t& r2,
                                      uint32_t& r3, uint32_t addr) {
    asm volatile("ldmatrix.sync.aligned.m8n8.x4.shared.b16 {%0,%1,%2,%3}, [%4];"
                 : "=r"(r0), "=r"(r1), "=r"(r2), "=r"(r3) : "r"(addr));
}

__device__ __forceinline__ void mma_tf32(float* d, const uint32_t* a, const uint32_t* b) {
    asm volatile(
        "mma.sync.aligned.m16n8k8.row.col.f32.tf32.tf32.f32 "
        "{%0,%1,%2,%3}, {%4,%5,%6,%7}, {%8,%9}, {%0,%1,%2,%3};"
        : "+f"(d[0]), "+f"(d[1]), "+f"(d[2]), "+f"(d[3])
        : "r"(a[0]), "r"(a[1]), "r"(a[2]), "r"(a[3]), "r"(b[0]), "r"(b[1]));
}

// -------------------- tf32 mma.sync GEMM (inputs pre-rounded) ---------------
// C[m,n] = sum_k A[m,k]*B[n,k] (+bias[n]). A: MxK row-major, B: NxK row-major.
__global__ void __launch_bounds__(512, 2)
gemm_tf32mma(const float* __restrict__ A, const float* __restrict__ Bm,
             const float* __restrict__ bias, float* __restrict__ C,
             int add_bias)
{
    extern __shared__ float sm[];
    const int tid = threadIdx.x;
    const int wid = tid >> 5, lid = tid & 31;
    const int g = lid >> 2, tg = lid & 3;       // mma quad coords
    const int warp_m = wid & 3;                 // 0..3 (32 rows)
    const int warp_n = wid >> 2;                // 0..3 (32 cols)
    const int bm = blockIdx.y * BM, bn = blockIdx.x * BN;

    const uint32_t sbase = smem_u32(sm);

    // ldmatrix per-lane source rows/cols
    // A x4 tiles: (r0,k0),(r0+8,k0),(r0,k0+4),(r0+8,k0+4)
    const int laneRowA = lid & 15;
    const int laneColA = (lid >> 4) << 2;
    // B x4 tiles: (n0,k0),(n0,k0+4),(n0+8,k0),(n0+8,k0+4)
    const int laneRowB = (lid & 7) + ((lid >> 4) << 3);
    const int laneColB = ((lid >> 3) & 1) << 2;

    const uint32_t aoff = (uint32_t)((warp_m * 32 + laneRowA) * LDT + laneColA) * 4u;
    const uint32_t boff = (uint32_t)((BM + warp_n * 32 + laneRowB) * LDT + laneColB) * 4u;

    float acc[2][4][4];
#pragma unroll
    for (int mi = 0; mi < 2; mi++)
#pragma unroll
        for (int ni = 0; ni < 4; ni++)
#pragma unroll
            for (int q = 0; q < 4; q++) acc[mi][ni][q] = 0.0f;

    auto load_stage = [&](int buf, int kt) {
        const uint32_t sa = sbase + (uint32_t)(buf * STAGEF) * 4u;
        const uint32_t sb2 = sa + (uint32_t)(BM * LDT) * 4u;
        const float* Ag = A + (size_t)bm * DIM + kt * BK;
        const float* Bg = Bm + (size_t)bn * DIM + kt * BK;
#pragma unroll
        for (int it = 0; it < 2; it++) {        // A: 128 rows x 8 chunks of 16B
            int idx = tid + it * 512;
            int r = idx >> 3, c = idx & 7;
            CP_ASYNC16(sa + (uint32_t)(r * LDT + c * 4) * 4u, Ag + (size_t)r * DIM + c * 4);
        }
#pragma unroll
        for (int it = 0; it < 2; it++) {        // B: 128 rows x 8 chunks
            int idx = tid + it * 512;
            int r = idx >> 3, c = idx & 7;
            CP_ASYNC16(sb2 + (uint32_t)(r * LDT + c * 4) * 4u, Bg + (size_t)r * DIM + c * 4);
        }
        asm volatile("cp.async.commit_group;" ::: "memory");
    };

    load_stage(0, 0);
    load_stage(1, 1);

    for (int j = 0; j < KTILES; j++) {
        if (j == KTILES - 1) asm volatile("cp.async.wait_group 0;" ::: "memory");
        else                 asm volatile("cp.async.wait_group 1;" ::: "memory");
        __syncthreads();

        if (j + 2 < KTILES) load_stage((j + 2) % NSTAGES, j + 2);

        const uint32_t stg = sbase + (uint32_t)((j % NSTAGES) * STAGEF) * 4u;
        const uint32_t sa = stg + aoff;
        const uint32_t sb2 = stg + boff;

#pragma unroll
        for (int ks = 0; ks < 4; ks++) {
            const uint32_t kb = (uint32_t)(ks * 8) * 4u;   // k0 in bytes
            uint32_t a[2][4], b[4][2];
#pragma unroll
            for (int mi = 0; mi < 2; mi++)
                ldsm4(a[mi][0], a[mi][1], a[mi][2], a[mi][3],
                      sa + kb + (uint32_t)(mi * 16 * LDT) * 4u);
            ldsm4(b[0][0], b[0][1], b[1][0], b[1][1], sb2 + kb);
            ldsm4(b[2][0], b[2][1], b[3][0], b[3][1],
                  sb2 + kb + (uint32_t)(16 * LDT) * 4u);
#pragma unroll
            for (int mi = 0; mi < 2; mi++)
#pragma unroll
                for (int ni = 0; ni < 4; ni++)
                    mma_tf32(acc[mi][ni], a[mi], b[ni]);
        }
        // no trailing sync: 3-stage ring; buffer written at iter j+1 was last
        // read at iter j-1, ordered by the barrier at top of iter j+1.
    }

    // ---- epilogue ----
#pragma unroll
    for (int mi = 0; mi < 2; mi++) {
        const int r0 = bm + warp_m * 32 + mi * 16 + g;
#pragma unroll
        for (int ni = 0; ni < 4; ni++) {
            const int cc = bn + warp_n * 32 + ni * 8 + 2 * tg;
            float2 v0 = make_float2(acc[mi][ni][0], acc[mi][ni][1]);
            float2 v1 = make_float2(acc[mi][ni][2], acc[mi][ni][3]);
            if (add_bias) {
                const float b0 = bias[cc], b1 = bias[cc + 1];
                v0.x += b0; v0.y += b1;
                v1.x += b0; v1.y += b1;
            }
            *reinterpret_cast<float2*>(&C[(size_t)r0 * DIM + cc]) = v0;
            *reinterpret_cast<float2*>(&C[(size_t)(r0 + 8) * DIM + cc]) = v1;
        }
    }
}

// -------------------- tf32 rounding prepass --------------------------------
__global__ void __launch_bounds__(256)
round_tf32_kernel(const float4* __restrict__ in, float4* __restrict__ out, int n4)
{
    int i = blockIdx.x * blockDim.x + threadIdx.x;
    if (i < n4) {
        float4 v = in[i];
        v.x = rtf32(v.x); v.y = rtf32(v.y); v.z = rtf32(v.z); v.w = rtf32(v.w);
        out[i] = v;
    }
}

// -------------------- chunked diagonal scan (in place on g_u) --------------
__global__ void __launch_bounds__(256)
scan_carry(const float* __restrict__ Avec)
{
    const int idx = blockIdx.x * blockDim.x + threadIdx.x;  // 131072
    const int n = idx & (DIM - 1);
    const int ch = (idx >> 10) & (CHUNKS - 1);
    const int b = idx >> 14;
    const float a = Avec[n];
    const float* u = g_u + ((size_t)b * SEQ + (size_t)ch * CLEN) * DIM + n;
    float h = 0.0f;
#pragma unroll 8
    for (int t = 0; t < CLEN; t++) h = fmaf(a, h, u[(size_t)t * DIM]);
    g_carry[idx] = h;
}

// prefix from carries (<=15 L2-resident reads), replay, store tf32-rounded h
__global__ void __launch_bounds__(256)
scan_apply(const float* __restrict__ Avec)
{
    const int idx = blockIdx.x * blockDim.x + threadIdx.x;  // 131072
    const int n = idx & (DIM - 1);
    const int ch = (idx >> 10) & (CHUNKS - 1);
    const int b = idx >> 14;
    const float a = Avec[n];

    float aL = a;
#pragma unroll
    for (int s = 0; s < 7; s++) aL *= aL;   // a^128

    float h = 0.0f;  // prefix entering this chunk
    for (int i = 0; i < ch; i++)
        h = fmaf(aL, h, g_carry[(b * CHUNKS + i) * DIM + n]);

    float* u = g_u + ((size_t)b * SEQ + (size_t)ch * CLEN) * DIM + n;
#pragma unroll 8
    for (int t = 0; t < CLEN; t++) {
        h = fmaf(a, h, u[(size_t)t * DIM]);
        u[(size_t)t * DIM] = rtf32(h);
    }
}

// -------------------- launch -----------------------------------------------
extern "C" void kernel_launch(void* const* d_in, const int* in_sizes, int n_in,
                              void* d_out, int out_size)
{
    const float* x    = (const float*)d_in[0];
    const float* Avec = (const float*)d_in[1];
    const float* Bmat = (const float*)d_in[2];
    const float* Wmat = (const float*)d_in[3];
    const float* bias = (const float*)d_in[4];
    float* out = (float*)d_out;

    float *u, *xr, *Br, *Wr;
    cudaGetSymbolAddress((void**)&u, g_u);
    cudaGetSymbolAddress((void**)&xr, g_x);
    cudaGetSymbolAddress((void**)&Br, g_Br);
    cudaGetSymbolAddress((void**)&Wr, g_Wr);

    cudaFuncSetAttribute(gemm_tf32mma, cudaFuncAttributeMaxDynamicSharedMemorySize, SMEM_BYTES);

    // pre-round inputs to tf32 (rna): keeps cvt out of GEMM hot loops
    const int nx4 = M_TOTAL * DIM / 4;
    const int nw4 = DIM * DIM / 4;
    round_tf32_kernel<<<(nx4 + 255) / 256, 256>>>((const float4*)x, (float4*)xr, nx4);
    round_tf32_kernel<<<(nw4 + 255) / 256, 256>>>((const float4*)Bmat, (float4*)Br, nw4);
    round_tf32_kernel<<<(nw4 + 255) / 256, 256>>>((const float4*)Wmat, (float4*)Wr, nw4);

    dim3 grid(DIM / BN, M_TOTAL / BM);  // (8, 128)

    // u = x_r @ B_r^T
    gemm_tf32mma<<<grid, 512, SMEM_BYTES>>>(xr, Br, nullptr, u, 0);

    // h_t = a h_{t-1} + u_t, chunked, in place; h stored tf32-rounded
    scan_carry<<<(BATCH * CHUNKS * DIM) / 256, 256>>>(Avec);
    scan_apply<<<(BATCH * CHUNKS * DIM) / 256, 256>>>(Avec);

    // y = h_r @ W_r^T + b
    gemm_tf32mma<<<grid, 512, SMEM_BYTES>>>(u, Wr, bias, out, 1);
}

// round 11
// speedup vs baseline: 1.3266x; 1.0394x over previous
#include <cuda_runtime.h>
#include <cstdint>

#define BATCH 8
#define SEQ 2048
#define DIM 1024
#define M_TOTAL (BATCH * SEQ)

// GEMM: warp-specialized, 576 threads (16 consumer warps + 2 producer warps)
#define BM 128
#define BN 128
#define BK 32
#define KTILES (DIM / BK)        // 32
#define LDT 36                   // padded smem row (floats); LDSM phases conflict-free
#define STAGEF ((BM + BN) * LDT) // floats per stage (A tile + B tile)
#define NSTAGES 4
#define THREADS 576
#define NCONS 512                // consumer threads
// smem: [0,32) full mbarriers, [32,64) empty mbarriers, [64,...) stage data
#define SMEM_DATA 64
#define SMEM_BYTES (SMEM_DATA + NSTAGES * STAGEF * 4)   // 147520

// scan chunking
#define CHUNKS 16
#define CLEN (SEQ / CHUNKS)      // 128

// -------------------- scratch (static device globals, no alloc) ------------
__device__ float g_u[(size_t)M_TOTAL * DIM];   // u, then h (tf32-rounded) in place
__device__ float g_x[(size_t)M_TOTAL * DIM];   // tf32-rounded x
__device__ float g_Br[DIM * DIM];              // tf32-rounded B
__device__ float g_Wr[DIM * DIM];              // tf32-rounded W
__device__ float g_carry[BATCH * CHUNKS * DIM];

// -------------------- helpers ----------------------------------------------
__device__ __forceinline__ uint32_t smem_u32(const void* p) {
    uint32_t a;
    asm("{ .reg .u64 t; cvta.to.shared.u64 t, %1; cvt.u32.u64 %0, t; }" : "=r"(a) : "l"(p));
    return a;
}
__device__ __forceinline__ float rtf32(float x) {
    uint32_t r;
    asm("cvt.rna.tf32.f32 %0, %1;" : "=r"(r) : "f"(x));
    return __uint_as_float(r);
}
#define CP_ASYNC16(dst, src) \
    asm volatile("cp.async.cg.shared.global [%0], [%1], 16;" :: "r"(dst), "l"(src))

#define MBAR_INIT(addr, cnt) \
    asm volatile("mbarrier.init.shared.b64 [%0], %1;" :: "r"(addr), "r"(cnt) : "memory")

#define MBAR_ARRIVE(addr) \
    asm volatile("mbarrier.arrive.shared.b64 _, [%0];" :: "r"(addr) : "memory")

#define CP_ASYNC_MBAR_ARRIVE(addr) \
    asm volatile("cp.async.mbarrier.arrive.noinc.shared.b64 [%0];" :: "r"(addr) : "memory")

#define MBAR_WAIT(addr, parity) do {                                            \
    asm volatile("{\n\t.reg .pred P1;\n\t"                                      \
        "WL_%=:\n\t"                                                            \
        "mbarrier.try_wait.parity.shared.b64 P1, [%0], %1, 0x989680;\n\t"       \
        "@P1 bra.uni WD_%=;\n\t"                                                \
        "bra.uni WL_%=;\n\t"                                                    \
        "WD_%=:\n\t}"                                                           \
        :: "r"(addr), "r"(parity) : "memory");                                  \
} while (0)

__device__ __forceinline__ void ldsm4(uint32_t& r0, uint32_t& r1, uint32_t& r2,
                                      uint32_t& r3, uint32_t addr) {
    asm volatile("ldmatrix.sync.aligned.m8n8.x4.shared.b16 {%0,%1,%2,%3}, [%4];"
                 : "=r"(r0), "=r"(r1), "=r"(r2), "=r"(r3) : "r"(addr));
}

__device__ __forceinline__ void mma_tf32(float* d, const uint32_t* a, const uint32_t* b) {
    asm volatile(
        "mma.sync.aligned.m16n8k8.row.col.f32.tf32.tf32.f32 "
        "{%0,%1,%2,%3}, {%4,%5,%6,%7}, {%8,%9}, {%0,%1,%2,%3};"
        : "+f"(d[0]), "+f"(d[1]), "+f"(d[2]), "+f"(d[3])
        : "r"(a[0]), "r"(a[1]), "r"(a[2]), "r"(a[3]), "r"(b[0]), "r"(b[1]));
}

// -------------------- warp-specialized tf32 mma.sync GEMM -------------------
// C[m,n] = sum_k A[m,k]*B[n,k] (+bias[n]). A: MxK row-major, B: NxK row-major.
// Inputs pre-rounded to tf32. No __syncthreads in the mainloop: producers
// (warps 16-17) fill a 4-stage cp.async ring; consumers (warps 0-15) wait
// per-stage mbarriers independently.
__global__ void __launch_bounds__(THREADS, 1)
gemm_tf32mma(const float* __restrict__ A, const float* __restrict__ Bm,
             const float* __restrict__ bias, float* __restrict__ C,
             int add_bias)
{
    extern __shared__ float sm[];
    const uint32_t sb = smem_u32(sm);
    const int tid = threadIdx.x;
    const int wid = tid >> 5, lid = tid & 31;
    const int bm = blockIdx.y * BM, bn = blockIdx.x * BN;

    if (tid == 0) {
#pragma unroll
        for (int s = 0; s < NSTAGES; s++) {
            MBAR_INIT(sb + s * 8, 64);        // full: 64 producer-thread async arrives
            MBAR_INIT(sb + 32 + s * 8, 16);   // empty: 16 consumer-warp arrives
        }
    }
    __syncthreads();   // one-time: mbarriers visible

    if (wid >= 16) {
        // ---------------- producer: 2 warps, 64 threads ----------------
        const int ptid = tid - NCONS;   // 0..63
        for (int j = 0; j < KTILES; j++) {
            const int s = j & (NSTAGES - 1);
            if (j >= NSTAGES)            // wait consumers done with use (j>>2)-1
                MBAR_WAIT(sb + 32 + s * 8, ((j >> 2) - 1) & 1);
            const uint32_t dst = sb + SMEM_DATA + (uint32_t)(s * STAGEF) * 4u;
            const float* Ag = A + (size_t)bm * DIM + j * BK;
            const float* Bg = Bm + (size_t)bn * DIM + j * BK;
#pragma unroll
            for (int it = 0; it < 32; it++) {
                const int idx = ptid + it * 64;
                const int r = idx >> 3, c = idx & 7;   // r: 0..255 (A then B)
                const float* src = (it < 16) ? (Ag + (size_t)r * DIM + c * 4)
                                             : (Bg + (size_t)(r - 128) * DIM + c * 4);
                CP_ASYNC16(dst + (uint32_t)(r * LDT + c * 4) * 4u, src);
            }
            CP_ASYNC_MBAR_ARRIVE(sb + s * 8);  // arrive full[s] when copies land
        }
        return;
    }

    // ---------------- consumer: 16 warps, 32x32 tiles ----------------
    const int g = lid >> 2, tg = lid & 3;
    const int warp_m = wid & 3;                 // 0..3 (32 rows)
    const int warp_n = wid >> 2;                // 0..3 (32 cols)

    // ldmatrix per-lane source rows/cols
    const int laneRowA = lid & 15;
    const int laneColA = (lid >> 4) << 2;
    const int laneRowB = (lid & 7) + ((lid >> 4) << 3);
    const int laneColB = ((lid >> 3) & 1) << 2;

    const uint32_t aoff = (uint32_t)((warp_m * 32 + laneRowA) * LDT + laneColA) * 4u;
    const uint32_t boff = (uint32_t)((BM + warp_n * 32 + laneRowB) * LDT + laneColB) * 4u;

    float acc[2][4][4];
#pragma unroll
    for (int mi = 0; mi < 2; mi++)
#pragma unroll
        for (int ni = 0; ni < 4; ni++)
#pragma unroll
            for (int q = 0; q < 4; q++) acc[mi][ni][q] = 0.0f;

    for (int j = 0; j < KTILES; j++) {
        const int s = j & (NSTAGES - 1);
        MBAR_WAIT(sb + s * 8, (j >> 2) & 1);   // full[s], fill #(j>>2)

        const uint32_t stg = sb + SMEM_DATA + (uint32_t)(s * STAGEF) * 4u;
        const uint32_t sa = stg + aoff;
        const uint32_t sb2 = stg + boff;

#pragma unroll
        for (int ks = 0; ks < 4; ks++) {
            const uint32_t kb = (uint32_t)(ks * 8) * 4u;
            uint32_t a[2][4], b[4][2];
#pragma unroll
            for (int mi = 0; mi < 2; mi++)
                ldsm4(a[mi][0], a[mi][1], a[mi][2], a[mi][3],
                      sa + kb + (uint32_t)(mi * 16 * LDT) * 4u);
            ldsm4(b[0][0], b[0][1], b[1][0], b[1][1], sb2 + kb);
            ldsm4(b[2][0], b[2][1], b[3][0], b[3][1],
                  sb2 + kb + (uint32_t)(16 * LDT) * 4u);
#pragma unroll
            for (int mi = 0; mi < 2; mi++)
#pragma unroll
                for (int ni = 0; ni < 4; ni++)
                    mma_tf32(acc[mi][ni], a[mi], b[ni]);
        }
        __syncwarp();
        if (lid == 0) MBAR_ARRIVE(sb + 32 + s * 8);   // empty[s]
    }

    // ---- epilogue ----
#pragma unroll
    for (int mi = 0; mi < 2; mi++) {
        const int r0 = bm + warp_m * 32 + mi * 16 + g;
#pragma unroll
        for (int ni = 0; ni < 4; ni++) {
            const int cc = bn + warp_n * 32 + ni * 8 + 2 * tg;
            float2 v0 = make_float2(acc[mi][ni][0], acc[mi][ni][1]);
            float2 v1 = make_float2(acc[mi][ni][2], acc[mi][ni][3]);
            if (add_bias) {
                const float b0 = bias[cc], b1 = bias[cc + 1];
                v0.x += b0; v0.y += b1;
                v1.x += b0; v1.y += b1;
            }
            *reinterpret_cast<float2*>(&C[(size_t)r0 * DIM + cc]) = v0;
            *reinterpret_cast<float2*>(&C[(size_t)(r0 + 8) * DIM + cc]) = v1;
        }
    }
}

// -------------------- tf32 rounding prepass --------------------------------
__global__ void __launch_bounds__(256)
round_tf32_kernel(const float4* __restrict__ in, float4* __restrict__ out, int n4)
{
    int i = blockIdx.x * blockDim.x + threadIdx.x;
    if (i < n4) {
        float4 v = in[i];
        v.x = rtf32(v.x); v.y = rtf32(v.y); v.z = rtf32(v.z); v.w = rtf32(v.w);
        out[i] = v;
    }
}

// -------------------- chunked diagonal scan (in place on g_u) --------------
__global__ void __launch_bounds__(256)
scan_carry(const float* __restrict__ Avec)
{
    const int idx = blockIdx.x * blockDim.x + threadIdx.x;  // 131072
    const int n = idx & (DIM - 1);
    const int ch = (idx >> 10) & (CHUNKS - 1);
    const int b = idx >> 14;
    const float a = Avec[n];
    const float* u = g_u + ((size_t)b * SEQ + (size_t)ch * CLEN) * DIM + n;
    float h = 0.0f;
#pragma unroll 8
    for (int t = 0; t < CLEN; t++) h = fmaf(a, h, u[(size_t)t * DIM]);
    g_carry[idx] = h;
}

// prefix from carries (<=15 L2-resident reads), replay, store tf32-rounded h
__global__ void __launch_bounds__(256)
scan_apply(const float* __restrict__ Avec)
{
    const int idx = blockIdx.x * blockDim.x + threadIdx.x;  // 131072
    const int n = idx & (DIM - 1);
    const int ch = (idx >> 10) & (CHUNKS - 1);
    const int b = idx >> 14;
    const float a = Avec[n];

    float aL = a;
#pragma unroll
    for (int s = 0; s < 7; s++) aL *= aL;   // a^128

    float h = 0.0f;  // prefix entering this chunk
    for (int i = 0; i < ch; i++)
        h = fmaf(aL, h, g_carry[(b * CHUNKS + i) * DIM + n]);

    float* u = g_u + ((size_t)b * SEQ + (size_t)ch * CLEN) * DIM + n;
#pragma unroll 8
    for (int t = 0; t < CLEN; t++) {
        h = fmaf(a, h, u[(size_t)t * DIM]);
        u[(size_t)t * DIM] = rtf32(h);
    }
}

// -------------------- launch -----------------------------------------------
extern "C" void kernel_launch(void* const* d_in, const int* in_sizes, int n_in,
                              void* d_out, int out_size)
{
    const float* x    = (const float*)d_in[0];
    const float* Avec = (const float*)d_in[1];
    const float* Bmat = (const float*)d_in[2];
    const float* Wmat = (const float*)d_in[3];
    const float* bias = (const float*)d_in[4];
    float* out = (float*)d_out;

    float *u, *xr, *Br, *Wr;
    cudaGetSymbolAddress((void**)&u, g_u);
    cudaGetSymbolAddress((void**)&xr, g_x);
    cudaGetSymbolAddress((void**)&Br, g_Br);
    cudaGetSymbolAddress((void**)&Wr, g_Wr);

    cudaFuncSetAttribute(gemm_tf32mma, cudaFuncAttributeMaxDynamicSharedMemorySize, SMEM_BYTES);

    // pre-round inputs to tf32 (rna): keeps cvt out of GEMM hot loops
    const int nx4 = M_TOTAL * DIM / 4;
    const int nw4 = DIM * DIM / 4;
    round_tf32_kernel<<<(nx4 + 255) / 256, 256>>>((const float4*)x, (float4*)xr, nx4);
    round_tf32_kernel<<<(nw4 + 255) / 256, 256>>>((const float4*)Bmat, (float4*)Br, nw4);
    round_tf32_kernel<<<(nw4 + 255) / 256, 256>>>((const float4*)Wmat, (float4*)Wr, nw4);

    dim3 grid(DIM / BN, M_TOTAL / BM);  // (8, 128)

    // u = x_r @ B_r^T
    gemm_tf32mma<<<grid, THREADS, SMEM_BYTES>>>(xr, Br, nullptr, u, 0);

    // h_t = a h_{t-1} + u_t, chunked, in place; h stored tf32-rounded
    scan_carry<<<(BATCH * CHUNKS * DIM) / 256, 256>>>(Avec);
    scan_apply<<<(BATCH * CHUNKS * DIM) / 256, 256>>>(Avec);

    // y = h_r @ W_r^T + b
    gemm_tf32mma<<<grid, THREADS, SMEM_BYTES>>>(u, Wr, bias, out, 1);
}